// round 12
// baseline (speedup 1.0000x reference)
#include <cuda_runtime.h>
#include <cuda_bf16.h>
#include <math.h>

#define Fn 500
#define Hn 2000
#define FH 2500
#define Dn 64
#define Bn 4096
#define NW 80            // bitmask words per row
#define NJC 4            // j-chunks of 640

// Scratch
__device__ __align__(16) float g_U[Fn * 128];     // [P1=wu*a^2 | P2=wu*a]
__device__ __align__(16) float g_V[FH * 128];     // [b | b^2]
__device__ float g_B[FH];
__device__ __align__(16) float g_pre_f[Fn * Dn];
__device__ unsigned g_mbits[Fn * NW];
__device__ __align__(16) float g_ctx_part[NJC][Fn][Dn];
__device__ float g_ssum_part[Fn][NJC];
__device__ __align__(16) float g_ctx[Fn * Dn];
__device__ int g_maxa_bits = 0;   // idempotent across replays (same inputs)
__device__ int g_maxb_bits = 0;
__device__ float g_sink;          // keeps prefetch loads alive

typedef unsigned long long ull;
__device__ __forceinline__ ull pk2(float a, float b) {
    ull r; asm("mov.b64 %0, {%1,%2};" : "=l"(r) : "f"(a), "f"(b)); return r;
}
__device__ __forceinline__ void upk2(ull v, float& a, float& b) {
    asm("mov.b64 {%0,%1}, %2;" : "=f"(a), "=f"(b) : "l"(v));
}
__device__ __forceinline__ ull f2fma(ull a, ull b, ull c) {
    ull d; asm("fma.rn.f32x2 %0, %1, %2, %3;" : "=l"(d) : "l"(a), "l"(b), "l"(c)); return d;
}
__device__ __forceinline__ const float* full_row(const float* feat,
                                                 const float* hid, int j) {
    return (j < Fn) ? (feat + j * Dn) : (hid + (j - Fn) * Dn);
}

// ---------------------------------------------------------------------------
// K1: blk 0..63     : stream `values` through L2 (prefetch for k4)
//     blk 64..688   : pre_w rows -> V=[b,b^2], B_j, maxb          (625)
//     blk 689..813  : pre_f rows -> U, pre_f, maxa                (125)
//     blk 814..970  : mask -> bitmask (float4, MLP 8)             (157)
// ---------------------------------------------------------------------------
__global__ __launch_bounds__(256) void k1(const float* __restrict__ values,
                                          const float* __restrict__ feat,
                                          const float* __restrict__ hid,
                                          const float* __restrict__ Ww,
                                          const float* __restrict__ bw,
                                          const float* __restrict__ Wu,
                                          const float* __restrict__ mask)
{
    __shared__ float sx[4][Dn];
    __shared__ float s_red[8];
    __shared__ float s_rmax[8];

    const int blk  = blockIdx.x;
    const int tid  = threadIdx.x;
    const int g    = tid >> 6;
    const int a    = tid & 63;
    const int wid  = tid >> 5;
    const int lane = tid & 31;

    if (blk < 64) {
        const float4* src = (const float4*)values;
        float s = 0.f;
        for (int idx = blk * 256 + tid; idx < 512000; idx += 64 * 256) {
            float4 v = __ldg(&src[idx]);
            s += (v.x + v.y) + (v.z + v.w);
        }
        if (s == 1.2345678e38f) g_sink = s;   // never true; keeps loads
    } else if (blk < 689) {
        const int row = (blk - 64) * 4 + g;             // j: 0..2499
        float v = (row < Fn) ? feat[row * Dn + a] : hid[(row - Fn) * Dn + a];
        sx[g][a] = v;
        __syncthreads();
        float bacc = 0.f;
        #pragma unroll
        for (int k = 0; k < Dn; k++)
            bacc += sx[g][k] * __ldg(&Ww[(Dn + k) * Dn + a]);
        const float wua = __ldg(&Wu[a]);
        const float b2 = bacc * bacc;
        g_V[row * 128 + a]      = bacc;
        g_V[row * 128 + 64 + a] = b2;
        float term = wua * (bacc - bacc * b2 * 0.33333334f);
        float mm = fabsf(bacc);
        #pragma unroll
        for (int off = 16; off > 0; off >>= 1) {
            term += __shfl_xor_sync(0xffffffffu, term, off);
            mm = fmaxf(mm, __shfl_xor_sync(0xffffffffu, mm, off));
        }
        if (lane == 0) { s_red[wid] = term; s_rmax[wid] = mm; }
        __syncthreads();
        if (tid < 4)
            g_B[(blk - 64) * 4 + tid] = s_red[2 * tid] + s_red[2 * tid + 1];
        if (tid == 0) {
            float mx = fmaxf(fmaxf(s_rmax[0], s_rmax[1]),
                             fmaxf(s_rmax[2], s_rmax[3]));
            mx = fmaxf(mx, fmaxf(fmaxf(s_rmax[4], s_rmax[5]),
                                 fmaxf(s_rmax[6], s_rmax[7])));
            atomicMax(&g_maxb_bits, __float_as_int(mx));
        }
    } else if (blk < 814) {
        const int row = (blk - 689) * 4 + g;            // i: 0..499
        sx[g][a] = feat[row * Dn + a];
        __syncthreads();
        float av = __ldg(&bw[a]);
        #pragma unroll
        for (int k = 0; k < Dn; k++)
            av += sx[g][k] * __ldg(&Ww[k * Dn + a]);
        const float wua = __ldg(&Wu[a]);
        g_pre_f[row * Dn + a]   = av;
        g_U[row * 128 + a]      = wua * av * av;
        g_U[row * 128 + 64 + a] = wua * av;
        float mm = fabsf(av);
        #pragma unroll
        for (int off = 16; off > 0; off >>= 1)
            mm = fmaxf(mm, __shfl_xor_sync(0xffffffffu, mm, off));
        if (lane == 0) s_rmax[wid] = mm;
        __syncthreads();
        if (tid == 0) {
            float mx = fmaxf(fmaxf(s_rmax[0], s_rmax[1]),
                             fmaxf(s_rmax[2], s_rmax[3]));
            mx = fmaxf(mx, fmaxf(fmaxf(s_rmax[4], s_rmax[5]),
                                 fmaxf(s_rmax[6], s_rmax[7])));
            atomicMax(&g_maxa_bits, __float_as_int(mx));
        }
    } else {
        const int gw = (blk - 814) * 256 + tid;         // word index
        if (gw < Fn * NW) {
            const int i = gw / NW;
            const int w = gw - i * NW;
            const int j0 = w * 32;
            const float* mrow = mask + (size_t)i * FH;
            unsigned word = 0;
            if (j0 + 32 <= FH) {
                const float4* m4 = (const float4*)(mrow + j0);
                #pragma unroll
                for (int q = 0; q < 8; q++) {
                    float4 v = __ldg(&m4[q]);
                    if (v.x != 0.f) word |= (1u << (q * 4 + 0));
                    if (v.y != 0.f) word |= (1u << (q * 4 + 1));
                    if (v.z != 0.f) word |= (1u << (q * 4 + 2));
                    if (v.w != 0.f) word |= (1u << (q * 4 + 3));
                }
            } else {
                for (int t = 0; t < 32; t++) {
                    int j = j0 + t;
                    if (j < FH && __ldg(&mrow[j]) != 0.0f) word |= (1u << t);
                }
            }
            g_mbits[gw] = word;
        }
    }
}

// ---------------------------------------------------------------------------
// K2: 2000 blocks = 500 i x 4 j-chunks. (verbatim R9/R11 — measured fast)
// ---------------------------------------------------------------------------
__global__ __launch_bounds__(128) void k2(const float* __restrict__ feat,
                                          const float* __restrict__ hid,
                                          const float* __restrict__ Wu)
{
    __shared__ __align__(16) float s_U[128];
    __shared__ __align__(16) float s_pf[Dn];
    __shared__ __align__(16) float s_wu[Dn];
    __shared__ unsigned s_words[20];
    __shared__ unsigned short s_jlist[640];
    __shared__ float s_elist[640];
    __shared__ int   s_warpbase[5];
    __shared__ float s_wsum[4];
    __shared__ float s_part[2][Dn];
    __shared__ float s_swu;
    __shared__ int   s_exact;

    const int i    = blockIdx.x >> 2;
    const int jc   = blockIdx.x & 3;
    const int jbase = jc * 640;
    const int tid  = threadIdx.x;
    const int wid  = tid >> 5;
    const int lane = tid & 31;

    s_U[tid] = g_U[i * 128 + tid];
    if (tid < 20) s_words[tid] = g_mbits[i * NW + jc * 20 + tid];
    if (tid < Dn) {
        s_pf[tid] = g_pre_f[i * Dn + tid];
        s_wu[tid] = __ldg(&Wu[tid]);
    }
    __syncthreads();

    if (wid == 0) {
        float s = fabsf(s_wu[lane]) + fabsf(s_wu[lane + 32]);
        #pragma unroll
        for (int off = 16; off > 0; off >>= 1)
            s += __shfl_xor_sync(0xffffffffu, s, off);
        if (lane == 0) s_swu = s;
    }
    __syncthreads();
    if (tid == 0) {
        float bnd = __int_as_float(g_maxa_bits) + __int_as_float(g_maxb_bits);
        float b5 = bnd * bnd; b5 = b5 * b5 * bnd;
        s_exact = (0.1333334f * b5 * s_swu >= 1e-4f) ? 1 : 0;
    }

    unsigned flags = 0;
    #pragma unroll
    for (int c = 0; c < 5; c++) {
        const int jl = c * 128 + tid;
        const bool act = ((s_words[jl >> 5] >> (jl & 31)) & 1u) &&
                         (jbase + jl < FH);
        if (act) flags |= (1u << c);
    }
    const int cl = __popc(flags);
    int inc = cl;
    #pragma unroll
    for (int off = 1; off < 32; off <<= 1) {
        int v = __shfl_up_sync(0xffffffffu, inc, off);
        if (lane >= off) inc += v;
    }
    if (lane == 31) s_warpbase[wid + 1] = inc;
    __syncthreads();
    if (tid == 0) {
        s_warpbase[0] = 0;
        #pragma unroll
        for (int w = 1; w <= 4; w++) s_warpbase[w] += s_warpbase[w - 1];
    }
    __syncthreads();
    {
        int off = s_warpbase[wid] + inc - cl;
        #pragma unroll
        for (int c = 0; c < 5; c++)
            if ((flags >> c) & 1u)
                s_jlist[off++] = (unsigned short)(c * 128 + tid);
    }
    __syncthreads();
    const int cnt = s_warpbase[4];

    float wsum = 0.f;
    if (!s_exact) {
        const ull* P1u = (const ull*)s_U;
        const ull* P2u = (const ull*)(s_U + 64);
        for (int m = tid; m < cnt; m += 128) {
            const int j = jbase + (int)s_jlist[m];
            const float4* vr = (const float4*)(g_V + j * 128);
            ull acc = 0ull;
            #pragma unroll
            for (int q = 0; q < 16; q++) {
                float4 b4 = __ldg(vr + q);
                ull b01 = pk2(b4.x, b4.y);
                ull b23 = pk2(b4.z, b4.w);
                ull t01 = f2fma(P2u[2 * q],     b01, P1u[2 * q]);
                ull t23 = f2fma(P2u[2 * q + 1], b23, P1u[2 * q + 1]);
                acc = f2fma(t01, b01, acc);
                acc = f2fma(t23, b23, acc);
            }
            float d0, d1; upk2(acc, d0, d1);
            float e = __expf(__ldg(&g_B[j]) - (d0 + d1));
            s_elist[m] = e;
            wsum += e;
        }
    } else {
        for (int m = tid; m < cnt; m += 128) {
            const int j = jbase + (int)s_jlist[m];
            const float* vr = g_V + j * 128;
            float s = 0.f;
            for (int k = 0; k < Dn; k++)
                s += tanhf(s_pf[k] + vr[k]) * s_wu[k];
            float e = expf(s);
            s_elist[m] = e;
            wsum += e;
        }
    }
    #pragma unroll
    for (int off = 16; off > 0; off >>= 1)
        wsum += __shfl_xor_sync(0xffffffffu, wsum, off);
    if (lane == 0) s_wsum[wid] = wsum;
    __syncthreads();
    if (tid == 0)
        g_ssum_part[i][jc] = (s_wsum[0] + s_wsum[1]) + (s_wsum[2] + s_wsum[3]);

    {
        const int gg = tid >> 6;
        const int k  = tid & 63;
        float a0 = 0.f, a1 = 0.f, a2 = 0.f, a3 = 0.f;
        float a4 = 0.f, a5 = 0.f, a6 = 0.f, a7 = 0.f;
        int m = gg;
        for (; m + 14 < cnt; m += 16) {
            a0 += s_elist[m]      * __ldg(full_row(feat, hid, jbase + (int)s_jlist[m])      + k);
            a1 += s_elist[m + 2]  * __ldg(full_row(feat, hid, jbase + (int)s_jlist[m + 2])  + k);
            a2 += s_elist[m + 4]  * __ldg(full_row(feat, hid, jbase + (int)s_jlist[m + 4])  + k);
            a3 += s_elist[m + 6]  * __ldg(full_row(feat, hid, jbase + (int)s_jlist[m + 6])  + k);
            a4 += s_elist[m + 8]  * __ldg(full_row(feat, hid, jbase + (int)s_jlist[m + 8])  + k);
            a5 += s_elist[m + 10] * __ldg(full_row(feat, hid, jbase + (int)s_jlist[m + 10]) + k);
            a6 += s_elist[m + 12] * __ldg(full_row(feat, hid, jbase + (int)s_jlist[m + 12]) + k);
            a7 += s_elist[m + 14] * __ldg(full_row(feat, hid, jbase + (int)s_jlist[m + 14]) + k);
        }
        for (; m < cnt; m += 2)
            a0 += s_elist[m] * __ldg(full_row(feat, hid, jbase + (int)s_jlist[m]) + k);
        s_part[gg][k] = ((a0 + a1) + (a2 + a3)) + ((a4 + a5) + (a6 + a7));
        __syncthreads();
        if (tid < Dn)
            g_ctx_part[jc][i][tid] = s_part[0][tid] + s_part[1][tid];
    }
}

// ---------------------------------------------------------------------------
// K3: reduce partials. 125 blocks x 256.
// ---------------------------------------------------------------------------
__global__ __launch_bounds__(256) void k3()
{
    const int i = blockIdx.x * 4 + (threadIdx.x >> 6);
    const int k = threadIdx.x & 63;
    float ss = (g_ssum_part[i][0] + g_ssum_part[i][1]) +
               (g_ssum_part[i][2] + g_ssum_part[i][3]);
    const float inv = (ss > 0.f) ? (1.0f / ss) : 1.0f;
    float c = (g_ctx_part[0][i][k] + g_ctx_part[1][i][k]) +
              (g_ctx_part[2][i][k] + g_ctx_part[3][i][k]);
    g_ctx[i * Dn + k] = c * inv;
}

// ---------------------------------------------------------------------------
// K4: out = values @ ctx. Barrier-free register-blocked GEMV batch.
// 256 blocks x 128 threads. Thread = 2 rows x 4 cols; ~30 loads in flight.
// ---------------------------------------------------------------------------
__global__ __launch_bounds__(128) void k4(const float* __restrict__ values,
                                          float* __restrict__ out)
{
    const int tid  = threadIdx.x;
    const int rp   = tid >> 4;           // 0..7 (row pair)
    const int cg   = tid & 15;           // col group
    const int c0   = cg * 4;
    const int row0 = blockIdx.x * 16 + rp * 2;

    const float4* vr0 = (const float4*)(values + (size_t)row0 * Fn);
    const float4* vr1 = (const float4*)(values + (size_t)(row0 + 1) * Fn);

    ull a00 = 0ull, a01 = 0ull;          // row0 cols c0..c0+3
    ull a10 = 0ull, a11 = 0ull;          // row1

    #pragma unroll 1
    for (int t = 0; t < 25; t++) {       // 25 chunks of 20 f
        float4 v0[5], v1[5];
        #pragma unroll
        for (int u = 0; u < 5; u++) {
            v0[u] = __ldg(&vr0[t * 5 + u]);
            v1[u] = __ldg(&vr1[t * 5 + u]);
        }
        #pragma unroll
        for (int u = 0; u < 5; u++) {
            const int fb = t * 20 + u * 4;
            #pragma unroll
            for (int w = 0; w < 4; w++) {
                const float vf0 = (w == 0) ? v0[u].x : (w == 1) ? v0[u].y :
                                  (w == 2) ? v0[u].z : v0[u].w;
                const float vf1 = (w == 0) ? v1[u].x : (w == 1) ? v1[u].y :
                                  (w == 2) ? v1[u].z : v1[u].w;
                const ull* cp = (const ull*)&g_ctx[(fb + w) * Dn + c0];
                ull cA = cp[0], cB = cp[1];
                a00 = f2fma(pk2(vf0, vf0), cA, a00);
                a01 = f2fma(pk2(vf0, vf0), cB, a01);
                a10 = f2fma(pk2(vf1, vf1), cA, a10);
                a11 = f2fma(pk2(vf1, vf1), cB, a11);
            }
        }
    }

    float a, b, c, d;
    upk2(a00, a, b); upk2(a01, c, d);
    *(float4*)&out[(size_t)row0 * Dn + c0] = make_float4(a, b, c, d);
    upk2(a10, a, b); upk2(a11, c, d);
    *(float4*)&out[(size_t)(row0 + 1) * Dn + c0] = make_float4(a, b, c, d);
}

// ---------------------------------------------------------------------------
extern "C" void kernel_launch(void* const* d_in, const int* in_sizes, int n_in,
                              void* d_out, int out_size)
{
    const float* values   = (const float*)d_in[0];
    const float* feat_emb = (const float*)d_in[1];
    const float* hid_emb  = (const float*)d_in[2];
    const float* Ww       = (const float*)d_in[3];
    const float* bw       = (const float*)d_in[4];
    const float* Wu       = (const float*)d_in[5];
    const float* mask     = (const float*)d_in[6];
    float* out            = (float*)d_out;

    k1<<<971, 256>>>(values, feat_emb, hid_emb, Ww, bw, Wu, mask);
    k2<<<2000, 128>>>(feat_emb, hid_emb, Wu);
    k3<<<125, 256>>>();
    k4<<<256, 128>>>(values, out);
}

// round 13
// speedup vs baseline: 1.7158x; 1.7158x over previous
#include <cuda_runtime.h>
#include <cuda_bf16.h>
#include <math.h>

#define Fn 500
#define Hn 2000
#define FH 2500
#define Dn 64
#define Bn 4096
#define NW 80            // bitmask words per row
#define NJC 4            // j-chunks of 640

// Scratch
__device__ __align__(16) float g_U[Fn * 128];     // [P1=wu*a^2 | P2=wu*a]
__device__ __align__(16) float g_V[FH * 128];     // [b | b^2]
__device__ float g_B[FH];
__device__ __align__(16) float g_pre_f[Fn * Dn];
__device__ unsigned g_mbits[Fn * NW];
__device__ __align__(16) float g_ctx_part[NJC][Fn][Dn];
__device__ float g_ssum_part[Fn][NJC];
__device__ __align__(16) float g_ctx[Fn * Dn];
__device__ int g_maxa_bits = 0;   // idempotent across replays (same inputs)
__device__ int g_maxb_bits = 0;
__device__ float g_sink;          // keeps prefetch loads alive

typedef unsigned long long ull;
__device__ __forceinline__ ull pk2(float a, float b) {
    ull r; asm("mov.b64 %0, {%1,%2};" : "=l"(r) : "f"(a), "f"(b)); return r;
}
__device__ __forceinline__ void upk2(ull v, float& a, float& b) {
    asm("mov.b64 {%0,%1}, %2;" : "=f"(a), "=f"(b) : "l"(v));
}
__device__ __forceinline__ ull f2fma(ull a, ull b, ull c) {
    ull d; asm("fma.rn.f32x2 %0, %1, %2, %3;" : "=l"(d) : "l"(a), "l"(b), "l"(c)); return d;
}
__device__ __forceinline__ const float* full_row(const float* feat,
                                                 const float* hid, int j) {
    return (j < Fn) ? (feat + j * Dn) : (hid + (j - Fn) * Dn);
}

// ---------------------------------------------------------------------------
// K1: blk 0..63     : stream `values` through L2 (prefetch for k4)
//     blk 64..688   : pre_w rows -> V=[b,b^2], B_j, maxb          (625)
//     blk 689..813  : pre_f rows -> U, pre_f, maxa                (125)
//     blk 814..970  : mask -> bitmask (float4, MLP 8)             (157)
// ---------------------------------------------------------------------------
__global__ __launch_bounds__(256) void k1(const float* __restrict__ values,
                                          const float* __restrict__ feat,
                                          const float* __restrict__ hid,
                                          const float* __restrict__ Ww,
                                          const float* __restrict__ bw,
                                          const float* __restrict__ Wu,
                                          const float* __restrict__ mask)
{
    __shared__ float sx[4][Dn];
    __shared__ float s_red[8];
    __shared__ float s_rmax[8];

    const int blk  = blockIdx.x;
    const int tid  = threadIdx.x;
    const int g    = tid >> 6;
    const int a    = tid & 63;
    const int wid  = tid >> 5;
    const int lane = tid & 31;

    if (blk < 64) {
        // values prefetch: 4 independent chains, batched loads
        const float4* src = (const float4*)values;
        float s0 = 0.f, s1 = 0.f, s2 = 0.f, s3 = 0.f;
        int idx = blk * 256 + tid;
        for (; idx + 3 * 16384 < 512000; idx += 4 * 16384) {
            float4 v0 = __ldg(&src[idx]);
            float4 v1 = __ldg(&src[idx + 16384]);
            float4 v2 = __ldg(&src[idx + 2 * 16384]);
            float4 v3 = __ldg(&src[idx + 3 * 16384]);
            s0 += (v0.x + v0.y) + (v0.z + v0.w);
            s1 += (v1.x + v1.y) + (v1.z + v1.w);
            s2 += (v2.x + v2.y) + (v2.z + v2.w);
            s3 += (v3.x + v3.y) + (v3.z + v3.w);
        }
        for (; idx < 512000; idx += 16384) {
            float4 v = __ldg(&src[idx]);
            s0 += (v.x + v.y) + (v.z + v.w);
        }
        float s = (s0 + s1) + (s2 + s3);
        if (s == 1.2345678e38f) g_sink = s;   // never true; keeps loads
    } else if (blk < 689) {
        const int row = (blk - 64) * 4 + g;             // j: 0..2499
        float v = (row < Fn) ? feat[row * Dn + a] : hid[(row - Fn) * Dn + a];
        sx[g][a] = v;
        __syncthreads();
        float bacc = 0.f;
        #pragma unroll
        for (int k = 0; k < Dn; k++)
            bacc += sx[g][k] * __ldg(&Ww[(Dn + k) * Dn + a]);
        const float wua = __ldg(&Wu[a]);
        const float b2 = bacc * bacc;
        g_V[row * 128 + a]      = bacc;
        g_V[row * 128 + 64 + a] = b2;
        float term = wua * (bacc - bacc * b2 * 0.33333334f);
        float mm = fabsf(bacc);
        #pragma unroll
        for (int off = 16; off > 0; off >>= 1) {
            term += __shfl_xor_sync(0xffffffffu, term, off);
            mm = fmaxf(mm, __shfl_xor_sync(0xffffffffu, mm, off));
        }
        if (lane == 0) { s_red[wid] = term; s_rmax[wid] = mm; }
        __syncthreads();
        if (tid < 4)
            g_B[(blk - 64) * 4 + tid] = s_red[2 * tid] + s_red[2 * tid + 1];
        if (tid == 0) {
            float mx = fmaxf(fmaxf(s_rmax[0], s_rmax[1]),
                             fmaxf(s_rmax[2], s_rmax[3]));
            mx = fmaxf(mx, fmaxf(fmaxf(s_rmax[4], s_rmax[5]),
                                 fmaxf(s_rmax[6], s_rmax[7])));
            atomicMax(&g_maxb_bits, __float_as_int(mx));
        }
    } else if (blk < 814) {
        const int row = (blk - 689) * 4 + g;            // i: 0..499
        sx[g][a] = feat[row * Dn + a];
        __syncthreads();
        float av = __ldg(&bw[a]);
        #pragma unroll
        for (int k = 0; k < Dn; k++)
            av += sx[g][k] * __ldg(&Ww[k * Dn + a]);
        const float wua = __ldg(&Wu[a]);
        g_pre_f[row * Dn + a]   = av;
        g_U[row * 128 + a]      = wua * av * av;
        g_U[row * 128 + 64 + a] = wua * av;
        float mm = fabsf(av);
        #pragma unroll
        for (int off = 16; off > 0; off >>= 1)
            mm = fmaxf(mm, __shfl_xor_sync(0xffffffffu, mm, off));
        if (lane == 0) s_rmax[wid] = mm;
        __syncthreads();
        if (tid == 0) {
            float mx = fmaxf(fmaxf(s_rmax[0], s_rmax[1]),
                             fmaxf(s_rmax[2], s_rmax[3]));
            mx = fmaxf(mx, fmaxf(fmaxf(s_rmax[4], s_rmax[5]),
                                 fmaxf(s_rmax[6], s_rmax[7])));
            atomicMax(&g_maxa_bits, __float_as_int(mx));
        }
    } else {
        const int gw = (blk - 814) * 256 + tid;         // word index
        if (gw < Fn * NW) {
            const int i = gw / NW;
            const int w = gw - i * NW;
            const int j0 = w * 32;
            const float* mrow = mask + (size_t)i * FH;
            unsigned word = 0;
            if (j0 + 32 <= FH) {
                const float4* m4 = (const float4*)(mrow + j0);
                #pragma unroll
                for (int q = 0; q < 8; q++) {
                    float4 v = __ldg(&m4[q]);
                    if (v.x != 0.f) word |= (1u << (q * 4 + 0));
                    if (v.y != 0.f) word |= (1u << (q * 4 + 1));
                    if (v.z != 0.f) word |= (1u << (q * 4 + 2));
                    if (v.w != 0.f) word |= (1u << (q * 4 + 3));
                }
            } else {
                for (int t = 0; t < 32; t++) {
                    int j = j0 + t;
                    if (j < FH && __ldg(&mrow[j]) != 0.0f) word |= (1u << t);
                }
            }
            g_mbits[gw] = word;
        }
    }
}

// ---------------------------------------------------------------------------
// K2: 2000 blocks = 500 i x 4 j-chunks. (verbatim — measured fast)
// ---------------------------------------------------------------------------
__global__ __launch_bounds__(128) void k2(const float* __restrict__ feat,
                                          const float* __restrict__ hid,
                                          const float* __restrict__ Wu)
{
    __shared__ __align__(16) float s_U[128];
    __shared__ __align__(16) float s_pf[Dn];
    __shared__ __align__(16) float s_wu[Dn];
    __shared__ unsigned s_words[20];
    __shared__ unsigned short s_jlist[640];
    __shared__ float s_elist[640];
    __shared__ int   s_warpbase[5];
    __shared__ float s_wsum[4];
    __shared__ float s_part[2][Dn];
    __shared__ float s_swu;
    __shared__ int   s_exact;

    const int i    = blockIdx.x >> 2;
    const int jc   = blockIdx.x & 3;
    const int jbase = jc * 640;
    const int tid  = threadIdx.x;
    const int wid  = tid >> 5;
    const int lane = tid & 31;

    s_U[tid] = g_U[i * 128 + tid];
    if (tid < 20) s_words[tid] = g_mbits[i * NW + jc * 20 + tid];
    if (tid < Dn) {
        s_pf[tid] = g_pre_f[i * Dn + tid];
        s_wu[tid] = __ldg(&Wu[tid]);
    }
    __syncthreads();

    if (wid == 0) {
        float s = fabsf(s_wu[lane]) + fabsf(s_wu[lane + 32]);
        #pragma unroll
        for (int off = 16; off > 0; off >>= 1)
            s += __shfl_xor_sync(0xffffffffu, s, off);
        if (lane == 0) s_swu = s;
    }
    __syncthreads();
    if (tid == 0) {
        float bnd = __int_as_float(g_maxa_bits) + __int_as_float(g_maxb_bits);
        float b5 = bnd * bnd; b5 = b5 * b5 * bnd;
        s_exact = (0.1333334f * b5 * s_swu >= 1e-4f) ? 1 : 0;
    }

    unsigned flags = 0;
    #pragma unroll
    for (int c = 0; c < 5; c++) {
        const int jl = c * 128 + tid;
        const bool act = ((s_words[jl >> 5] >> (jl & 31)) & 1u) &&
                         (jbase + jl < FH);
        if (act) flags |= (1u << c);
    }
    const int cl = __popc(flags);
    int inc = cl;
    #pragma unroll
    for (int off = 1; off < 32; off <<= 1) {
        int v = __shfl_up_sync(0xffffffffu, inc, off);
        if (lane >= off) inc += v;
    }
    if (lane == 31) s_warpbase[wid + 1] = inc;
    __syncthreads();
    if (tid == 0) {
        s_warpbase[0] = 0;
        #pragma unroll
        for (int w = 1; w <= 4; w++) s_warpbase[w] += s_warpbase[w - 1];
    }
    __syncthreads();
    {
        int off = s_warpbase[wid] + inc - cl;
        #pragma unroll
        for (int c = 0; c < 5; c++)
            if ((flags >> c) & 1u)
                s_jlist[off++] = (unsigned short)(c * 128 + tid);
    }
    __syncthreads();
    const int cnt = s_warpbase[4];

    float wsum = 0.f;
    if (!s_exact) {
        const ull* P1u = (const ull*)s_U;
        const ull* P2u = (const ull*)(s_U + 64);
        for (int m = tid; m < cnt; m += 128) {
            const int j = jbase + (int)s_jlist[m];
            const float4* vr = (const float4*)(g_V + j * 128);
            ull acc = 0ull;
            #pragma unroll
            for (int q = 0; q < 16; q++) {
                float4 b4 = __ldg(vr + q);
                ull b01 = pk2(b4.x, b4.y);
                ull b23 = pk2(b4.z, b4.w);
                ull t01 = f2fma(P2u[2 * q],     b01, P1u[2 * q]);
                ull t23 = f2fma(P2u[2 * q + 1], b23, P1u[2 * q + 1]);
                acc = f2fma(t01, b01, acc);
                acc = f2fma(t23, b23, acc);
            }
            float d0, d1; upk2(acc, d0, d1);
            float e = __expf(__ldg(&g_B[j]) - (d0 + d1));
            s_elist[m] = e;
            wsum += e;
        }
    } else {
        for (int m = tid; m < cnt; m += 128) {
            const int j = jbase + (int)s_jlist[m];
            const float* vr = g_V + j * 128;
            float s = 0.f;
            for (int k = 0; k < Dn; k++)
                s += tanhf(s_pf[k] + vr[k]) * s_wu[k];
            float e = expf(s);
            s_elist[m] = e;
            wsum += e;
        }
    }
    #pragma unroll
    for (int off = 16; off > 0; off >>= 1)
        wsum += __shfl_xor_sync(0xffffffffu, wsum, off);
    if (lane == 0) s_wsum[wid] = wsum;
    __syncthreads();
    if (tid == 0)
        g_ssum_part[i][jc] = (s_wsum[0] + s_wsum[1]) + (s_wsum[2] + s_wsum[3]);

    {
        const int gg = tid >> 6;
        const int k  = tid & 63;
        float a0 = 0.f, a1 = 0.f, a2 = 0.f, a3 = 0.f;
        float a4 = 0.f, a5 = 0.f, a6 = 0.f, a7 = 0.f;
        int m = gg;
        for (; m + 14 < cnt; m += 16) {
            a0 += s_elist[m]      * __ldg(full_row(feat, hid, jbase + (int)s_jlist[m])      + k);
            a1 += s_elist[m + 2]  * __ldg(full_row(feat, hid, jbase + (int)s_jlist[m + 2])  + k);
            a2 += s_elist[m + 4]  * __ldg(full_row(feat, hid, jbase + (int)s_jlist[m + 4])  + k);
            a3 += s_elist[m + 6]  * __ldg(full_row(feat, hid, jbase + (int)s_jlist[m + 6])  + k);
            a4 += s_elist[m + 8]  * __ldg(full_row(feat, hid, jbase + (int)s_jlist[m + 8])  + k);
            a5 += s_elist[m + 10] * __ldg(full_row(feat, hid, jbase + (int)s_jlist[m + 10]) + k);
            a6 += s_elist[m + 12] * __ldg(full_row(feat, hid, jbase + (int)s_jlist[m + 12]) + k);
            a7 += s_elist[m + 14] * __ldg(full_row(feat, hid, jbase + (int)s_jlist[m + 14]) + k);
        }
        for (; m < cnt; m += 2)
            a0 += s_elist[m] * __ldg(full_row(feat, hid, jbase + (int)s_jlist[m]) + k);
        s_part[gg][k] = ((a0 + a1) + (a2 + a3)) + ((a4 + a5) + (a6 + a7));
        __syncthreads();
        if (tid < Dn)
            g_ctx_part[jc][i][tid] = s_part[0][tid] + s_part[1][tid];
    }
}

// ---------------------------------------------------------------------------
// K3: reduce partials. 125 blocks x 256.
// ---------------------------------------------------------------------------
__global__ __launch_bounds__(256) void k3()
{
    const int i = blockIdx.x * 4 + (threadIdx.x >> 6);
    const int k = threadIdx.x & 63;
    float ss = (g_ssum_part[i][0] + g_ssum_part[i][1]) +
               (g_ssum_part[i][2] + g_ssum_part[i][3]);
    const float inv = (ss > 0.f) ? (1.0f / ss) : 1.0f;
    float c = (g_ctx_part[0][i][k] + g_ctx_part[1][i][k]) +
              (g_ctx_part[2][i][k] + g_ctx_part[3][i][k]);
    g_ctx[i * Dn + k] = c * inv;
}

// ---------------------------------------------------------------------------
// K4: out = values @ ctx. Double-buffered smem pipeline (R11 design),
// 512 blocks x 256 threads, 8 rows/block -> 4096 warps (2x R11 occupancy).
// ---------------------------------------------------------------------------
__global__ __launch_bounds__(256) void k4(const float* __restrict__ values,
                                          float* __restrict__ out)
{
    __shared__ __align__(16) float s_val[2][8][50];
    __shared__ __align__(16) float s_ctx[2][50][64];

    const int rb   = blockIdx.x;
    const int tid  = threadIdx.x;
    const int tx   = tid & 31;          // col pair
    const int ty   = tid >> 5;          // 0..7 -> row
    const int c0   = tx * 2;
    const int row  = rb * 8 + ty;

    // loader assignments: values 8*50=400 floats = 200 float2 (tid<200);
    // ctx 50*64=3200 floats = 800 float4 (tid + u*256, u<4, p<800)
    float2 vreg;
    float4 creg[4];
    const int vr0 = tid / 25, vc0 = tid - vr0 * 25;

    #define LOAD_TILE(t)                                                     \
        do {                                                                 \
            if (tid < 200)                                                   \
                vreg = *(const float2*)&values[(size_t)(rb * 8 + vr0) * Fn + \
                                               (t) * 50 + vc0 * 2];          \
            _Pragma("unroll")                                                \
            for (int u = 0; u < 4; u++) {                                    \
                int p = tid + u * 256;                                       \
                if (p < 800) {                                               \
                    int f = p >> 4, c4 = p & 15;                             \
                    creg[u] = *(const float4*)&g_ctx[((t) * 50 + f) * 64 +   \
                                                     c4 * 4];                \
                }                                                            \
            }                                                                \
        } while (0)

    #define STORE_TILE(buf)                                                  \
        do {                                                                 \
            if (tid < 200) *(float2*)&s_val[buf][vr0][vc0 * 2] = vreg;       \
            _Pragma("unroll")                                                \
            for (int u = 0; u < 4; u++) {                                    \
                int p = tid + u * 256;                                       \
                if (p < 800) {                                               \
                    int f = p >> 4, c4 = p & 15;                             \
                    *(float4*)&s_ctx[buf][f][c4 * 4] = creg[u];              \
                }                                                            \
            }                                                                \
        } while (0)

    LOAD_TILE(0);
    STORE_TILE(0);
    __syncthreads();

    ull a0 = 0ull;
    #pragma unroll
    for (int t = 0; t < 10; t++) {
        if (t + 1 < 10) LOAD_TILE(t + 1);
        const int b = t & 1;
        #pragma unroll
        for (int f = 0; f < 50; f++) {
            float v = s_val[b][ty][f];
            const ull* cp = (const ull*)&s_ctx[b][f][c0];
            a0 = f2fma(pk2(v, v), cp[0], a0);
        }
        __syncthreads();
        if (t + 1 < 10) {
            STORE_TILE((t + 1) & 1);
        }
        __syncthreads();
    }

    float a, b2;
    upk2(a0, a, b2);
    *(float2*)&out[(size_t)row * Dn + c0] = make_float2(a, b2);
}

// ---------------------------------------------------------------------------
extern "C" void kernel_launch(void* const* d_in, const int* in_sizes, int n_in,
                              void* d_out, int out_size)
{
    const float* values   = (const float*)d_in[0];
    const float* feat_emb = (const float*)d_in[1];
    const float* hid_emb  = (const float*)d_in[2];
    const float* Ww       = (const float*)d_in[3];
    const float* bw       = (const float*)d_in[4];
    const float* Wu       = (const float*)d_in[5];
    const float* mask     = (const float*)d_in[6];
    float* out            = (float*)d_out;

    k1<<<971, 256>>>(values, feat_emb, hid_emb, Ww, bw, Wu, mask);
    k2<<<2000, 128>>>(feat_emb, hid_emb, Wu);
    k3<<<125, 256>>>();
    k4<<<512, 256>>>(values, out);
}

// round 14
// speedup vs baseline: 1.8486x; 1.0774x over previous
#include <cuda_runtime.h>
#include <cuda_bf16.h>
#include <math.h>

#define Fn 500
#define Hn 2000
#define FH 2500
#define Dn 64
#define Bn 4096
#define NW 80            // bitmask words per row
#define NJC 4            // j-chunks of 640
#define FSPLIT 5
#define FCH 100          // f per split
#define TFQ 20           // f per tile

// Scratch
__device__ __align__(16) float g_U[Fn * 128];     // [P1=wu*a^2 | P2=wu*a]
__device__ __align__(16) float g_V[FH * 128];     // [b | b^2]
__device__ float g_B[FH];
__device__ __align__(16) float g_pre_f[Fn * Dn];
__device__ unsigned g_mbits[Fn * NW];
__device__ __align__(16) float g_ctx_part[NJC][Fn][Dn];
__device__ float g_ssum_part[Fn][NJC];
__device__ __align__(16) float g_ctx[Fn * Dn];
__device__ __align__(16) float g_out_part[FSPLIT][Bn][Dn];   // 5.2MB partials
__device__ int g_maxa_bits = 0;   // idempotent across replays (same inputs)
__device__ int g_maxb_bits = 0;
__device__ float g_sink;          // keeps prefetch loads alive

typedef unsigned long long ull;
__device__ __forceinline__ ull pk2(float a, float b) {
    ull r; asm("mov.b64 %0, {%1,%2};" : "=l"(r) : "f"(a), "f"(b)); return r;
}
__device__ __forceinline__ void upk2(ull v, float& a, float& b) {
    asm("mov.b64 {%0,%1}, %2;" : "=f"(a), "=f"(b) : "l"(v));
}
__device__ __forceinline__ ull f2fma(ull a, ull b, ull c) {
    ull d; asm("fma.rn.f32x2 %0, %1, %2, %3;" : "=l"(d) : "l"(a), "l"(b), "l"(c)); return d;
}
__device__ __forceinline__ const float* full_row(const float* feat,
                                                 const float* hid, int j) {
    return (j < Fn) ? (feat + j * Dn) : (hid + (j - Fn) * Dn);
}

// ---------------------------------------------------------------------------
// K1: blk 0..624   : pre_w rows -> V=[b,b^2], B_j, maxb
//     blk 625..749 : pre_f rows -> U, pre_f, maxa
//     blk 750..906 : mask -> bitmask (float4, MLP 8)
// ---------------------------------------------------------------------------
__global__ __launch_bounds__(256) void k1(const float* __restrict__ feat,
                                          const float* __restrict__ hid,
                                          const float* __restrict__ Ww,
                                          const float* __restrict__ bw,
                                          const float* __restrict__ Wu,
                                          const float* __restrict__ mask)
{
    __shared__ float sx[4][Dn];
    __shared__ float s_red[8];
    __shared__ float s_rmax[8];

    const int blk  = blockIdx.x;
    const int tid  = threadIdx.x;
    const int g    = tid >> 6;
    const int a    = tid & 63;
    const int wid  = tid >> 5;
    const int lane = tid & 31;

    if (blk < 625) {
        const int row = blk * 4 + g;                    // j: 0..2499
        float v = (row < Fn) ? feat[row * Dn + a] : hid[(row - Fn) * Dn + a];
        sx[g][a] = v;
        __syncthreads();
        float bacc = 0.f;
        #pragma unroll
        for (int k = 0; k < Dn; k++)
            bacc += sx[g][k] * __ldg(&Ww[(Dn + k) * Dn + a]);
        const float wua = __ldg(&Wu[a]);
        const float b2 = bacc * bacc;
        g_V[row * 128 + a]      = bacc;
        g_V[row * 128 + 64 + a] = b2;
        float term = wua * (bacc - bacc * b2 * 0.33333334f);
        float mm = fabsf(bacc);
        #pragma unroll
        for (int off = 16; off > 0; off >>= 1) {
            term += __shfl_xor_sync(0xffffffffu, term, off);
            mm = fmaxf(mm, __shfl_xor_sync(0xffffffffu, mm, off));
        }
        if (lane == 0) { s_red[wid] = term; s_rmax[wid] = mm; }
        __syncthreads();
        if (tid < 4)
            g_B[blk * 4 + tid] = s_red[2 * tid] + s_red[2 * tid + 1];
        if (tid == 0) {
            float mx = fmaxf(fmaxf(s_rmax[0], s_rmax[1]),
                             fmaxf(s_rmax[2], s_rmax[3]));
            mx = fmaxf(mx, fmaxf(fmaxf(s_rmax[4], s_rmax[5]),
                                 fmaxf(s_rmax[6], s_rmax[7])));
            atomicMax(&g_maxb_bits, __float_as_int(mx));
        }
    } else if (blk < 750) {
        const int row = (blk - 625) * 4 + g;            // i: 0..499
        sx[g][a] = feat[row * Dn + a];
        __syncthreads();
        float av = __ldg(&bw[a]);
        #pragma unroll
        for (int k = 0; k < Dn; k++)
            av += sx[g][k] * __ldg(&Ww[k * Dn + a]);
        const float wua = __ldg(&Wu[a]);
        g_pre_f[row * Dn + a]   = av;
        g_U[row * 128 + a]      = wua * av * av;
        g_U[row * 128 + 64 + a] = wua * av;
        float mm = fabsf(av);
        #pragma unroll
        for (int off = 16; off > 0; off >>= 1)
            mm = fmaxf(mm, __shfl_xor_sync(0xffffffffu, mm, off));
        if (lane == 0) s_rmax[wid] = mm;
        __syncthreads();
        if (tid == 0) {
            float mx = fmaxf(fmaxf(s_rmax[0], s_rmax[1]),
                             fmaxf(s_rmax[2], s_rmax[3]));
            mx = fmaxf(mx, fmaxf(fmaxf(s_rmax[4], s_rmax[5]),
                                 fmaxf(s_rmax[6], s_rmax[7])));
            atomicMax(&g_maxa_bits, __float_as_int(mx));
        }
    } else {
        const int gw = (blk - 750) * 256 + tid;         // word index
        if (gw < Fn * NW) {
            const int i = gw / NW;
            const int w = gw - i * NW;
            const int j0 = w * 32;
            const float* mrow = mask + (size_t)i * FH;
            unsigned word = 0;
            if (j0 + 32 <= FH) {
                const float4* m4 = (const float4*)(mrow + j0);
                #pragma unroll
                for (int q = 0; q < 8; q++) {
                    float4 v = __ldg(&m4[q]);
                    if (v.x != 0.f) word |= (1u << (q * 4 + 0));
                    if (v.y != 0.f) word |= (1u << (q * 4 + 1));
                    if (v.z != 0.f) word |= (1u << (q * 4 + 2));
                    if (v.w != 0.f) word |= (1u << (q * 4 + 3));
                }
            } else {
                for (int t = 0; t < 32; t++) {
                    int j = j0 + t;
                    if (j < FH && __ldg(&mrow[j]) != 0.0f) word |= (1u << t);
                }
            }
            g_mbits[gw] = word;
        }
    }
}

// ---------------------------------------------------------------------------
// K2: blk 0..1999 : attention (500 i x 4 j-chunks) — verbatim, measured fast
//     blk 2000..2511 : stream `values` through L2 (overlapped prefetch)
// ---------------------------------------------------------------------------
__global__ __launch_bounds__(128) void k2(const float* __restrict__ values,
                                          const float* __restrict__ feat,
                                          const float* __restrict__ hid,
                                          const float* __restrict__ Wu)
{
    __shared__ __align__(16) float s_U[128];
    __shared__ __align__(16) float s_pf[Dn];
    __shared__ __align__(16) float s_wu[Dn];
    __shared__ unsigned s_words[20];
    __shared__ unsigned short s_jlist[640];
    __shared__ float s_elist[640];
    __shared__ int   s_warpbase[5];
    __shared__ float s_wsum[4];
    __shared__ float s_part[2][Dn];
    __shared__ float s_swu;
    __shared__ int   s_exact;

    const int tid  = threadIdx.x;
    const int wid  = tid >> 5;
    const int lane = tid & 31;

    if (blockIdx.x >= 2000) {
        // values prefetch: 4 independent chains
        const float4* src = (const float4*)values;
        float s0 = 0.f, s1 = 0.f, s2 = 0.f, s3 = 0.f;
        int idx = (blockIdx.x - 2000) * 128 + tid;
        for (; idx + 3 * 65536 < 512000; idx += 4 * 65536) {
            float4 v0 = __ldg(&src[idx]);
            float4 v1 = __ldg(&src[idx + 65536]);
            float4 v2 = __ldg(&src[idx + 2 * 65536]);
            float4 v3 = __ldg(&src[idx + 3 * 65536]);
            s0 += (v0.x + v0.y) + (v0.z + v0.w);
            s1 += (v1.x + v1.y) + (v1.z + v1.w);
            s2 += (v2.x + v2.y) + (v2.z + v2.w);
            s3 += (v3.x + v3.y) + (v3.z + v3.w);
        }
        for (; idx < 512000; idx += 65536) {
            float4 v = __ldg(&src[idx]);
            s0 += (v.x + v.y) + (v.z + v.w);
        }
        float s = (s0 + s1) + (s2 + s3);
        if (s == 1.2345678e38f) g_sink = s;   // never true; keeps loads
        return;
    }

    const int i    = blockIdx.x >> 2;
    const int jc   = blockIdx.x & 3;
    const int jbase = jc * 640;

    s_U[tid] = g_U[i * 128 + tid];
    if (tid < 20) s_words[tid] = g_mbits[i * NW + jc * 20 + tid];
    if (tid < Dn) {
        s_pf[tid] = g_pre_f[i * Dn + tid];
        s_wu[tid] = __ldg(&Wu[tid]);
    }
    __syncthreads();

    if (wid == 0) {
        float s = fabsf(s_wu[lane]) + fabsf(s_wu[lane + 32]);
        #pragma unroll
        for (int off = 16; off > 0; off >>= 1)
            s += __shfl_xor_sync(0xffffffffu, s, off);
        if (lane == 0) s_swu = s;
    }
    __syncthreads();
    if (tid == 0) {
        float bnd = __int_as_float(g_maxa_bits) + __int_as_float(g_maxb_bits);
        float b5 = bnd * bnd; b5 = b5 * b5 * bnd;
        s_exact = (0.1333334f * b5 * s_swu >= 1e-4f) ? 1 : 0;
    }

    unsigned flags = 0;
    #pragma unroll
    for (int c = 0; c < 5; c++) {
        const int jl = c * 128 + tid;
        const bool act = ((s_words[jl >> 5] >> (jl & 31)) & 1u) &&
                         (jbase + jl < FH);
        if (act) flags |= (1u << c);
    }
    const int cl = __popc(flags);
    int inc = cl;
    #pragma unroll
    for (int off = 1; off < 32; off <<= 1) {
        int v = __shfl_up_sync(0xffffffffu, inc, off);
        if (lane >= off) inc += v;
    }
    if (lane == 31) s_warpbase[wid + 1] = inc;
    __syncthreads();
    if (tid == 0) {
        s_warpbase[0] = 0;
        #pragma unroll
        for (int w = 1; w <= 4; w++) s_warpbase[w] += s_warpbase[w - 1];
    }
    __syncthreads();
    {
        int off = s_warpbase[wid] + inc - cl;
        #pragma unroll
        for (int c = 0; c < 5; c++)
            if ((flags >> c) & 1u)
                s_jlist[off++] = (unsigned short)(c * 128 + tid);
    }
    __syncthreads();
    const int cnt = s_warpbase[4];

    float wsum = 0.f;
    if (!s_exact) {
        const ull* P1u = (const ull*)s_U;
        const ull* P2u = (const ull*)(s_U + 64);
        for (int m = tid; m < cnt; m += 128) {
            const int j = jbase + (int)s_jlist[m];
            const float4* vr = (const float4*)(g_V + j * 128);
            ull acc = 0ull;
            #pragma unroll
            for (int q = 0; q < 16; q++) {
                float4 b4 = __ldg(vr + q);
                ull b01 = pk2(b4.x, b4.y);
                ull b23 = pk2(b4.z, b4.w);
                ull t01 = f2fma(P2u[2 * q],     b01, P1u[2 * q]);
                ull t23 = f2fma(P2u[2 * q + 1], b23, P1u[2 * q + 1]);
                acc = f2fma(t01, b01, acc);
                acc = f2fma(t23, b23, acc);
            }
            float d0, d1; upk2(acc, d0, d1);
            float e = __expf(__ldg(&g_B[j]) - (d0 + d1));
            s_elist[m] = e;
            wsum += e;
        }
    } else {
        for (int m = tid; m < cnt; m += 128) {
            const int j = jbase + (int)s_jlist[m];
            const float* vr = g_V + j * 128;
            float s = 0.f;
            for (int k = 0; k < Dn; k++)
                s += tanhf(s_pf[k] + vr[k]) * s_wu[k];
            float e = expf(s);
            s_elist[m] = e;
            wsum += e;
        }
    }
    #pragma unroll
    for (int off = 16; off > 0; off >>= 1)
        wsum += __shfl_xor_sync(0xffffffffu, wsum, off);
    if (lane == 0) s_wsum[wid] = wsum;
    __syncthreads();
    if (tid == 0)
        g_ssum_part[i][jc] = (s_wsum[0] + s_wsum[1]) + (s_wsum[2] + s_wsum[3]);

    {
        const int gg = tid >> 6;
        const int k  = tid & 63;
        float a0 = 0.f, a1 = 0.f, a2 = 0.f, a3 = 0.f;
        float a4 = 0.f, a5 = 0.f, a6 = 0.f, a7 = 0.f;
        int m = gg;
        for (; m + 14 < cnt; m += 16) {
            a0 += s_elist[m]      * __ldg(full_row(feat, hid, jbase + (int)s_jlist[m])      + k);
            a1 += s_elist[m + 2]  * __ldg(full_row(feat, hid, jbase + (int)s_jlist[m + 2])  + k);
            a2 += s_elist[m + 4]  * __ldg(full_row(feat, hid, jbase + (int)s_jlist[m + 4])  + k);
            a3 += s_elist[m + 6]  * __ldg(full_row(feat, hid, jbase + (int)s_jlist[m + 6])  + k);
            a4 += s_elist[m + 8]  * __ldg(full_row(feat, hid, jbase + (int)s_jlist[m + 8])  + k);
            a5 += s_elist[m + 10] * __ldg(full_row(feat, hid, jbase + (int)s_jlist[m + 10]) + k);
            a6 += s_elist[m + 12] * __ldg(full_row(feat, hid, jbase + (int)s_jlist[m + 12]) + k);
            a7 += s_elist[m + 14] * __ldg(full_row(feat, hid, jbase + (int)s_jlist[m + 14]) + k);
        }
        for (; m < cnt; m += 2)
            a0 += s_elist[m] * __ldg(full_row(feat, hid, jbase + (int)s_jlist[m]) + k);
        s_part[gg][k] = ((a0 + a1) + (a2 + a3)) + ((a4 + a5) + (a6 + a7));
        __syncthreads();
        if (tid < Dn)
            g_ctx_part[jc][i][tid] = s_part[0][tid] + s_part[1][tid];
    }
}

// ---------------------------------------------------------------------------
// K3: reduce ctx partials. 125 blocks x 256.
// ---------------------------------------------------------------------------
__global__ __launch_bounds__(256) void k3()
{
    const int i = blockIdx.x * 4 + (threadIdx.x >> 6);
    const int k = threadIdx.x & 63;
    float ss = (g_ssum_part[i][0] + g_ssum_part[i][1]) +
               (g_ssum_part[i][2] + g_ssum_part[i][3]);
    const float inv = (ss > 0.f) ? (1.0f / ss) : 1.0f;
    float c = (g_ctx_part[0][i][k] + g_ctx_part[1][i][k]) +
              (g_ctx_part[2][i][k] + g_ctx_part[3][i][k]);
    g_ctx[i * Dn + k] = c * inv;
}

// ---------------------------------------------------------------------------
// K4a: out partials = values @ ctx, split-f by 5.
// 160 blocks (32 rowblocks x 5 fsplits) x 256 threads.
// Block tile 128 rows x 64 cols; thread = 4 rows x 8 cols (16 FFMA2 / f).
// Double-buffered smem tiles of TFQ=20 f.
// ---------------------------------------------------------------------------
__global__ __launch_bounds__(256) void k4a(const float* __restrict__ values)
{
    __shared__ __align__(16) float s_val[2][128][TFQ];
    __shared__ __align__(16) float s_ctx[2][TFQ][Dn];

    const int rb    = blockIdx.x / FSPLIT;     // 0..31
    const int fs    = blockIdx.x % FSPLIT;     // 0..4
    const int row0  = rb * 128;
    const int fbase = fs * FCH;
    const int tid   = threadIdx.x;
    const int rg    = tid >> 3;                // 0..31 (4 rows each)
    const int cg    = tid & 7;                 // 0..7  (8 cols each)
    const int r0    = rg * 4;
    const int c0    = cg * 8;

    // loader regs: values 128*5=640 float4/tile; ctx 20*16=320 float4/tile
    float4 vreg[3];
    float4 creg[2];

    #define K4_LOAD(t)                                                        \
        do {                                                                  \
            _Pragma("unroll")                                                 \
            for (int u = 0; u < 3; u++) {                                     \
                int q = tid + u * 256;                                        \
                if (q < 640) {                                                \
                    int r = q / 5, fc = q - r * 5;                            \
                    vreg[u] = *(const float4*)&values[                        \
                        (size_t)(row0 + r) * Fn + fbase + (t) * TFQ + fc * 4];\
                }                                                             \
            }                                                                 \
            _Pragma("unroll")                                                 \
            for (int u = 0; u < 2; u++) {                                     \
                int q = tid + u * 256;                                        \
                if (q < 320) {                                                \
                    int f = q >> 4, c4 = q & 15;                              \
                    creg[u] = *(const float4*)&g_ctx[                         \
                        (fbase + (t) * TFQ + f) * Dn + c4 * 4];               \
                }                                                             \
            }                                                                 \
        } while (0)

    #define K4_STORE(buf)                                                    \
        do {                                                                 \
            _Pragma("unroll")                                                \
            for (int u = 0; u < 3; u++) {                                    \
                int q = tid + u * 256;                                       \
                if (q < 640) {                                               \
                    int r = q / 5, fc = q - r * 5;                           \
                    *(float4*)&s_val[buf][r][fc * 4] = vreg[u];              \
                }                                                            \
            }                                                                \
            _Pragma("unroll")                                                \
            for (int u = 0; u < 2; u++) {                                    \
                int q = tid + u * 256;                                       \
                if (q < 320) {                                               \
                    int f = q >> 4, c4 = q & 15;                             \
                    *(float4*)&s_ctx[buf][f][c4 * 4] = creg[u];              \
                }                                                            \
            }                                                                \
        } while (0)

    ull acc[16];
    #pragma unroll
    for (int q = 0; q < 16; q++) acc[q] = 0ull;

    K4_LOAD(0);
    K4_STORE(0);
    __syncthreads();

    #pragma unroll
    for (int t = 0; t < FCH / TFQ; t++) {       // 5 tiles
        if (t + 1 < FCH / TFQ) K4_LOAD(t + 1);
        const int b = t & 1;
        #pragma unroll
        for (int f = 0; f < TFQ; f++) {
            float v0 = s_val[b][r0 + 0][f];
            float v1 = s_val[b][r0 + 1][f];
            float v2 = s_val[b][r0 + 2][f];
            float v3 = s_val[b][r0 + 3][f];
            const ull* cp = (const ull*)&s_ctx[b][f][c0];
            ull cA = cp[0], cB = cp[1], cC = cp[2], cD = cp[3];
            ull p0 = pk2(v0, v0), p1 = pk2(v1, v1);
            ull p2 = pk2(v2, v2), p3 = pk2(v3, v3);
            acc[0]  = f2fma(p0, cA, acc[0]);
            acc[1]  = f2fma(p0, cB, acc[1]);
            acc[2]  = f2fma(p0, cC, acc[2]);
            acc[3]  = f2fma(p0, cD, acc[3]);
            acc[4]  = f2fma(p1, cA, acc[4]);
            acc[5]  = f2fma(p1, cB, acc[5]);
            acc[6]  = f2fma(p1, cC, acc[6]);
            acc[7]  = f2fma(p1, cD, acc[7]);
            acc[8]  = f2fma(p2, cA, acc[8]);
            acc[9]  = f2fma(p2, cB, acc[9]);
            acc[10] = f2fma(p2, cC, acc[10]);
            acc[11] = f2fma(p2, cD, acc[11]);
            acc[12] = f2fma(p3, cA, acc[12]);
            acc[13] = f2fma(p3, cB, acc[13]);
            acc[14] = f2fma(p3, cC, acc[14]);
            acc[15] = f2fma(p3, cD, acc[15]);
        }
        __syncthreads();
        if (t + 1 < FCH / TFQ) {
            K4_STORE((t + 1) & 1);
        }
        __syncthreads();
    }

    #pragma unroll
    for (int r = 0; r < 4; r++) {
        float a, b, c, d, e, f2, g, h;
        upk2(acc[r * 4 + 0], a, b);
        upk2(acc[r * 4 + 1], c, d);
        upk2(acc[r * 4 + 2], e, f2);
        upk2(acc[r * 4 + 3], g, h);
        float* dst = &g_out_part[fs][row0 + r0 + r][c0];
        *(float4*)dst       = make_float4(a, b, c, d);
        *(float4*)(dst + 4) = make_float4(e, f2, g, h);
    }
}

// ---------------------------------------------------------------------------
// K4b: out = sum of 5 partials. 256 blocks x 256 threads, one float4 each.
// ---------------------------------------------------------------------------
__global__ __launch_bounds__(256) void k4b(float* __restrict__ out)
{
    const int idx = blockIdx.x * 256 + threadIdx.x;     // < 65536 float4
    const float4* p0 = (const float4*)&g_out_part[0][0][0];
    const float4* p1 = (const float4*)&g_out_part[1][0][0];
    const float4* p2 = (const float4*)&g_out_part[2][0][0];
    const float4* p3 = (const float4*)&g_out_part[3][0][0];
    const float4* p4 = (const float4*)&g_out_part[4][0][0];
    float4 a = __ldg(&p0[idx]);
    float4 b = __ldg(&p1[idx]);
    float4 c = __ldg(&p2[idx]);
    float4 d = __ldg(&p3[idx]);
    float4 e = __ldg(&p4[idx]);
    float4 r;
    r.x = ((a.x + b.x) + (c.x + d.x)) + e.x;
    r.y = ((a.y + b.y) + (c.y + d.y)) + e.y;
    r.z = ((a.z + b.z) + (c.z + d.z)) + e.z;
    r.w = ((a.w + b.w) + (c.w + d.w)) + e.w;
    ((float4*)out)[idx] = r;
}

// ---------------------------------------------------------------------------
extern "C" void kernel_launch(void* const* d_in, const int* in_sizes, int n_in,
                              void* d_out, int out_size)
{
    const float* values   = (const float*)d_in[0];
    const float* feat_emb = (const float*)d_in[1];
    const float* hid_emb  = (const float*)d_in[2];
    const float* Ww       = (const float*)d_in[3];
    const float* bw       = (const float*)d_in[4];
    const float* Wu       = (const float*)d_in[5];
    const float* mask     = (const float*)d_in[6];
    float* out            = (float*)d_out;

    k1<<<907, 256>>>(feat_emb, hid_emb, Ww, bw, Wu, mask);
    k2<<<2512, 128>>>(values, feat_emb, hid_emb, Wu);
    k3<<<125, 256>>>();
    k4a<<<160, 256>>>(values);
    k4b<<<256, 256>>>(out);
}